// round 1
// baseline (speedup 1.0000x reference)
#include <cuda_runtime.h>

#define S 256
#define C 128
#define H 4
#define D 32
#define NROW (S*S)
#define ATTN_SCALE 0.1767766952966369f   // 1/sqrt(32)
#define LN_EPS 1e-5f

// Scratch (device globals: allocation-free per harness rules)
__device__ float g_q[NROW*C];
__device__ float g_k[NROW*C];
__device__ float g_v[NROW*C];
__device__ float g_g[NROW*C];   // sigmoid(z @ Wg^T), gate already applied
__device__ float g_o[NROW*C];   // attention output

// ---------------------------------------------------------------------------
// Kernel A: fused LayerNorm + 4 projections (q,k,v,g). 32 rows per block.
// ---------------------------------------------------------------------------
__global__ __launch_bounds__(256) void proj_kernel(
    const float* __restrict__ z,
    const float* __restrict__ lnw, const float* __restrict__ lnb,
    const float* __restrict__ Wq, const float* __restrict__ Wk,
    const float* __restrict__ Wv, const float* __restrict__ Wg)
{
    __shared__ float sZt[C][33];   // [k][local row], 32 rows, pad 33 -> conflict-free
    __shared__ float sWt[C][33];   // [k][local col], 32 cols

    const int tid  = threadIdx.x;
    const int warp = tid >> 5;
    const int lane = tid & 31;
    const int r0   = blockIdx.x * 32;

    // ---- LayerNorm: 8 warps x 4 rows each ----
    #pragma unroll
    for (int rr = 0; rr < 4; rr++) {
        const int rl = warp * 4 + rr;
        const float* zr = z + (size_t)(r0 + rl) * C;
        float v0 = zr[lane], v1 = zr[lane+32], v2 = zr[lane+64], v3 = zr[lane+96];
        float s  = v0+v1+v2+v3;
        float sq = v0*v0+v1*v1+v2*v2+v3*v3;
        #pragma unroll
        for (int off = 16; off; off >>= 1) {
            s  += __shfl_xor_sync(0xffffffffu, s,  off);
            sq += __shfl_xor_sync(0xffffffffu, sq, off);
        }
        const float mu  = s * (1.0f/128.0f);
        const float var = sq * (1.0f/128.0f) - mu*mu;
        const float rs  = rsqrtf(var + LN_EPS);
        sZt[lane     ][rl] = (v0-mu)*rs*lnw[lane     ] + lnb[lane     ];
        sZt[lane + 32][rl] = (v1-mu)*rs*lnw[lane + 32] + lnb[lane + 32];
        sZt[lane + 64][rl] = (v2-mu)*rs*lnw[lane + 64] + lnb[lane + 64];
        sZt[lane + 96][rl] = (v3-mu)*rs*lnw[lane + 96] + lnb[lane + 96];
    }
    __syncthreads();

    const float* Ws[4] = {Wq, Wk, Wv, Wg};
    float*       Os[4] = {g_q, g_k, g_v, g_g};

    const int tr = tid >> 4;   // 0..15
    const int tc = tid & 15;   // 0..15

    for (int chunk = 0; chunk < 16; chunk++) {
        const int grp   = chunk >> 2;
        const int cbase = (chunk & 3) * 32;
        const float* W  = Ws[grp];

        __syncthreads();   // previous sWt fully consumed
        for (int idx = tid; idx < 32*128; idx += 256) {
            const int k = idx & 127, c = idx >> 7;
            sWt[k][c] = W[(cbase + c)*C + k];
        }
        __syncthreads();

        float a00 = 0.f, a01 = 0.f, a10 = 0.f, a11 = 0.f;
        #pragma unroll 16
        for (int k = 0; k < C; k++) {
            const float x0 = sZt[k][tr], x1 = sZt[k][tr+16];
            const float w0 = sWt[k][tc], w1 = sWt[k][tc+16];
            a00 += x0*w0; a01 += x0*w1; a10 += x1*w0; a11 += x1*w1;
        }
        if (grp == 3) {  // gate: apply sigmoid
            a00 = 1.0f/(1.0f + __expf(-a00));
            a01 = 1.0f/(1.0f + __expf(-a01));
            a10 = 1.0f/(1.0f + __expf(-a10));
            a11 = 1.0f/(1.0f + __expf(-a11));
        }
        float* O = Os[grp];
        O[(size_t)(r0+tr   )*C + cbase + tc     ] = a00;
        O[(size_t)(r0+tr   )*C + cbase + tc + 16] = a01;
        O[(size_t)(r0+tr+16)*C + cbase + tc     ] = a10;
        O[(size_t)(r0+tr+16)*C + cbase + tc + 16] = a11;
    }
}

// ---------------------------------------------------------------------------
// Kernel B: attention. One block per (j,h); thread t = query i=t.
// K (256x32 fp32, 32KB) resident in smem; V streamed in 64-row chunks (8KB).
// Online softmax with scalar-amortized rescale. Bias term dropped: it is
// constant over the softmax axis and therefore mathematically a no-op.
// ---------------------------------------------------------------------------
__global__ __launch_bounds__(256) void attn_kernel()
{
    __shared__ float sK[256][32];
    __shared__ float sV[64][32];

    const int j   = blockIdx.x;
    const int h   = blockIdx.y;
    const int tid = threadIdx.x;

    const size_t kvbase = (size_t)j * S * C + h * 32;   // row (j*S + k)

    // Load full K tile (coalesced: 8 threads per row, 16B each)
    for (int idx = tid; idx < 256*8; idx += 256) {
        const int row = idx >> 3, f4 = idx & 7;
        *(float4*)&sK[row][f4*4] =
            *(const float4*)(g_k + kvbase + (size_t)row * C + f4*4);
    }

    // Query into registers
    float q[32];
    const size_t qoff = ((size_t)tid * S + j) * C + h * 32;
    #pragma unroll
    for (int f4 = 0; f4 < 8; f4++) {
        float4 t = *(const float4*)(g_q + qoff + f4*4);
        q[f4*4+0] = t.x; q[f4*4+1] = t.y; q[f4*4+2] = t.z; q[f4*4+3] = t.w;
    }

    float m = -1e30f, l = 0.0f;
    float o[32];
    #pragma unroll
    for (int d = 0; d < 32; d++) o[d] = 0.0f;

    for (int ch = 0; ch < 4; ch++) {
        __syncthreads();
        for (int idx = tid; idx < 64*8; idx += 256) {
            const int row = idx >> 3, f4 = idx & 7;
            *(float4*)&sV[row][f4*4] =
                *(const float4*)(g_v + kvbase + (size_t)(ch*64 + row) * C + f4*4);
        }
        __syncthreads();

        for (int kk = 0; kk < 64; kk++) {
            const float* Kr = sK[ch*64 + kk];
            float s = 0.0f;
            #pragma unroll
            for (int d = 0; d < 32; d++) s += q[d] * Kr[d];
            s *= ATTN_SCALE;

            if (s > m) {             // rare after warmup (~6x per thread total)
                const float corr = __expf(m - s);
                l *= corr;
                #pragma unroll
                for (int d = 0; d < 32; d++) o[d] *= corr;
                m = s;
            }
            const float p = __expf(s - m);
            l += p;
            const float* Vr = sV[kk];
            #pragma unroll
            for (int d = 0; d < 32; d++) o[d] += p * Vr[d];
        }
    }

    const float inv = 1.0f / l;
    #pragma unroll
    for (int d = 0; d < 32; d++) g_o[qoff + d] = o[d] * inv;
}

// ---------------------------------------------------------------------------
// Kernel C: out = (g * o) @ Wo^T. Same GEMM structure as A; the elementwise
// gate product is fused into the tile-load stage.
// ---------------------------------------------------------------------------
__global__ __launch_bounds__(256) void out_kernel(
    const float* __restrict__ Wo, float* __restrict__ out)
{
    __shared__ float sZt[C][33];
    __shared__ float sWt[C][33];

    const int tid = threadIdx.x;
    const int r0  = blockIdx.x * 32;

    for (int idx = tid; idx < 32*128; idx += 256) {
        const int k = idx & 127, rl = idx >> 7;
        const size_t off = (size_t)(r0 + rl) * C + k;
        sZt[k][rl] = g_g[off] * g_o[off];
    }
    __syncthreads();

    const int tr = tid >> 4;
    const int tc = tid & 15;

    for (int chunk = 0; chunk < 4; chunk++) {
        const int cbase = chunk * 32;
        __syncthreads();
        for (int idx = tid; idx < 32*128; idx += 256) {
            const int k = idx & 127, c = idx >> 7;
            sWt[k][c] = Wo[(cbase + c)*C + k];
        }
        __syncthreads();

        float a00 = 0.f, a01 = 0.f, a10 = 0.f, a11 = 0.f;
        #pragma unroll 16
        for (int k = 0; k < C; k++) {
            const float x0 = sZt[k][tr], x1 = sZt[k][tr+16];
            const float w0 = sWt[k][tc], w1 = sWt[k][tc+16];
            a00 += x0*w0; a01 += x0*w1; a10 += x1*w0; a11 += x1*w1;
        }
        out[(size_t)(r0+tr   )*C + cbase + tc     ] = a00;
        out[(size_t)(r0+tr   )*C + cbase + tc + 16] = a01;
        out[(size_t)(r0+tr+16)*C + cbase + tc     ] = a10;
        out[(size_t)(r0+tr+16)*C + cbase + tc + 16] = a11;
    }
}

// ---------------------------------------------------------------------------
extern "C" void kernel_launch(void* const* d_in, const int* in_sizes, int n_in,
                              void* d_out, int out_size)
{
    const float* z   = (const float*)d_in[0];
    const float* lnw = (const float*)d_in[1];
    const float* lnb = (const float*)d_in[2];
    const float* Wq  = (const float*)d_in[3];
    const float* Wk  = (const float*)d_in[4];
    const float* Wv  = (const float*)d_in[5];
    // d_in[6] = Wb: bias is constant over the softmax axis -> exact no-op, skipped.
    const float* Wg  = (const float*)d_in[7];
    const float* Wo  = (const float*)d_in[8];
    float* out = (float*)d_out;

    proj_kernel<<<NROW/32, 256>>>(z, lnw, lnb, Wq, Wk, Wv, Wg);
    attn_kernel<<<dim3(S, H), 256>>>();
    out_kernel<<<NROW/32, 256>>>(Wo, out);
}

// round 2
// speedup vs baseline: 1.3196x; 1.3196x over previous
#include <cuda_runtime.h>

#define S 256
#define C 128
#define H 4
#define D 32
#define NROW (S*S)
#define ATTN_SCALE 0.1767766952966369f   // 1/sqrt(32)
#define LN_EPS 1e-5f

// Scratch (device globals: allocation-free per harness rules)
__device__ float g_q[NROW*C];
__device__ float g_k[NROW*C];
__device__ float g_v[NROW*C];
__device__ float g_g[NROW*C];            // sigmoid(z @ Wg^T)
__device__ float g_o[NROW*C];            // attention output
__device__ float g_Wt[5][C][C];          // k-major transposed weights: g_Wt[m][k][c] = W_m[c][k]

// ---------------------------------------------------------------------------
// Kernel T: transpose the 5 weight matrices into k-major layout (tiny).
// ---------------------------------------------------------------------------
__global__ void transpose_w(const float* __restrict__ Wq, const float* __restrict__ Wk,
                            const float* __restrict__ Wv, const float* __restrict__ Wg,
                            const float* __restrict__ Wo)
{
    __shared__ float t[32][33];
    const float* Ws[5] = {Wq, Wk, Wv, Wg, Wo};
    const float* W = Ws[blockIdx.z];
    const int cb = blockIdx.x * 32;
    const int kb = blockIdx.y * 32;
    const int tx = threadIdx.x, ty = threadIdx.y;

    #pragma unroll
    for (int i = ty; i < 32; i += 8)
        t[i][tx] = W[(cb + i) * C + kb + tx];
    __syncthreads();
    #pragma unroll
    for (int i = ty; i < 32; i += 8)
        g_Wt[blockIdx.z][kb + i][cb + tx] = t[tx][i];
}

// ---------------------------------------------------------------------------
// Kernel A: fused LayerNorm + 4 projections (q,k,v,g).
// Block tile: 64 rows x 128 cols per weight. 256 threads, 4x8 register tile.
// ---------------------------------------------------------------------------
__global__ __launch_bounds__(256) void proj_kernel(
    const float* __restrict__ z,
    const float* __restrict__ lnw, const float* __restrict__ lnb)
{
    __shared__ float sZ[C][68];    // [k][row], pad 68 -> 4-way-max write conflict, 16B aligned rows
    __shared__ float sW[16][C];    // [k][col] chunk

    const int tid  = threadIdx.x;
    const int warp = tid >> 5;
    const int lane = tid & 31;
    const int r0   = blockIdx.x * 64;

    // ---- LayerNorm: 8 warps x 8 rows each ----
    #pragma unroll
    for (int rr = 0; rr < 8; rr++) {
        const int rl = warp * 8 + rr;
        const float* zr = z + (size_t)(r0 + rl) * C;
        float v0 = zr[lane], v1 = zr[lane+32], v2 = zr[lane+64], v3 = zr[lane+96];
        float s  = v0+v1+v2+v3;
        float sq = v0*v0+v1*v1+v2*v2+v3*v3;
        #pragma unroll
        for (int off = 16; off; off >>= 1) {
            s  += __shfl_xor_sync(0xffffffffu, s,  off);
            sq += __shfl_xor_sync(0xffffffffu, sq, off);
        }
        const float mu  = s * (1.0f/128.0f);
        const float var = sq * (1.0f/128.0f) - mu*mu;
        const float rs  = rsqrtf(var + LN_EPS);
        sZ[lane     ][rl] = (v0-mu)*rs*lnw[lane     ] + lnb[lane     ];
        sZ[lane + 32][rl] = (v1-mu)*rs*lnw[lane + 32] + lnb[lane + 32];
        sZ[lane + 64][rl] = (v2-mu)*rs*lnw[lane + 64] + lnb[lane + 64];
        sZ[lane + 96][rl] = (v3-mu)*rs*lnw[lane + 96] + lnb[lane + 96];
    }
    __syncthreads();

    const int tr = tid >> 4;   // 0..15 -> rows tr*4 .. tr*4+3
    const int tc = tid & 15;   // 0..15 -> cols tc*8 .. tc*8+7

    for (int grp = 0; grp < 4; grp++) {
        float acc[32];
        #pragma unroll
        for (int i = 0; i < 32; i++) acc[i] = 0.0f;

        for (int kb = 0; kb < 8; kb++) {
            __syncthreads();
            #pragma unroll
            for (int l = 0; l < 8; l++) {
                const int idx = tid + l * 256;
                const int c = idx & 127, k = idx >> 7;
                sW[k][c] = g_Wt[grp][kb*16 + k][c];
            }
            __syncthreads();

            #pragma unroll
            for (int k = 0; k < 16; k++) {
                const float4 a  = *(const float4*)&sZ[kb*16 + k][tr*4];
                const float4 b0 = *(const float4*)&sW[k][tc*8];
                const float4 b1 = *(const float4*)&sW[k][tc*8 + 4];
                const float av[4] = {a.x, a.y, a.z, a.w};
                const float bv[8] = {b0.x,b0.y,b0.z,b0.w,b1.x,b1.y,b1.z,b1.w};
                #pragma unroll
                for (int r = 0; r < 4; r++)
                    #pragma unroll
                    for (int cc = 0; cc < 8; cc++)
                        acc[r*8+cc] += av[r] * bv[cc];
            }
        }

        float* O = (grp == 0) ? g_q : (grp == 1) ? g_k : (grp == 2) ? g_v : g_g;
        #pragma unroll
        for (int r = 0; r < 4; r++) {
            float v[8];
            #pragma unroll
            for (int cc = 0; cc < 8; cc++) v[cc] = acc[r*8+cc];
            if (grp == 3) {
                #pragma unroll
                for (int cc = 0; cc < 8; cc++) v[cc] = 1.0f/(1.0f + __expf(-v[cc]));
            }
            const size_t row = (size_t)(r0 + tr*4 + r);
            float4 o0 = {v[0],v[1],v[2],v[3]};
            float4 o1 = {v[4],v[5],v[6],v[7]};
            *(float4*)&O[row*C + tc*8    ] = o0;
            *(float4*)&O[row*C + tc*8 + 4] = o1;
        }
    }
}

// ---------------------------------------------------------------------------
// Kernel B: attention. Block = (j,h); 128 threads, 2 queries per thread.
// K fully resident (32KB), V in 2 chunks (16KB). Online softmax.
// Bias term dropped: constant over the softmax axis -> exact no-op.
// ---------------------------------------------------------------------------
__global__ __launch_bounds__(128) void attn_kernel()
{
    __shared__ float sK[256][32];
    __shared__ float sV[128][32];

    const int j   = blockIdx.x;
    const int h   = blockIdx.y;
    const int tid = threadIdx.x;

    const size_t kvbase = (size_t)j * S * C + h * 32;   // row (j*S + k)

    for (int idx = tid; idx < 256*8; idx += 128) {
        const int row = idx >> 3, f4 = idx & 7;
        *(float4*)&sK[row][f4*4] =
            *(const float4*)(g_k + kvbase + (size_t)row * C + f4*4);
    }

    // Two queries per thread: i0 = tid, i1 = tid + 128
    float q0[32], q1[32], o0[32], o1[32];
    const size_t q0off = ((size_t)tid * S + j) * C + h * 32;
    const size_t q1off = q0off + (size_t)128 * S * C;
    #pragma unroll
    for (int f = 0; f < 8; f++) {
        float4 t0 = *(const float4*)(g_q + q0off + f*4);
        float4 t1 = *(const float4*)(g_q + q1off + f*4);
        q0[f*4+0]=t0.x; q0[f*4+1]=t0.y; q0[f*4+2]=t0.z; q0[f*4+3]=t0.w;
        q1[f*4+0]=t1.x; q1[f*4+1]=t1.y; q1[f*4+2]=t1.z; q1[f*4+3]=t1.w;
    }
    #pragma unroll
    for (int d = 0; d < 32; d++) { o0[d] = 0.0f; o1[d] = 0.0f; }

    float m0 = -1e30f, l0 = 0.0f, m1 = -1e30f, l1 = 0.0f;

    for (int ch = 0; ch < 2; ch++) {
        __syncthreads();
        for (int idx = tid; idx < 128*8; idx += 128) {
            const int row = idx >> 3, f4 = idx & 7;
            *(float4*)&sV[row][f4*4] =
                *(const float4*)(g_v + kvbase + (size_t)(ch*128 + row) * C + f4*4);
        }
        __syncthreads();

        for (int kk = 0; kk < 128; kk++) {
            const float4* Kr = (const float4*)sK[ch*128 + kk];
            float s0 = 0.0f, s1 = 0.0f;
            #pragma unroll
            for (int f = 0; f < 8; f++) {
                const float4 kv = Kr[f];
                s0 += q0[f*4+0]*kv.x + q0[f*4+1]*kv.y + q0[f*4+2]*kv.z + q0[f*4+3]*kv.w;
                s1 += q1[f*4+0]*kv.x + q1[f*4+1]*kv.y + q1[f*4+2]*kv.z + q1[f*4+3]*kv.w;
            }
            s0 *= ATTN_SCALE; s1 *= ATTN_SCALE;

            if (s0 > m0) {
                const float corr = __expf(m0 - s0);
                l0 *= corr;
                #pragma unroll
                for (int d = 0; d < 32; d++) o0[d] *= corr;
                m0 = s0;
            }
            if (s1 > m1) {
                const float corr = __expf(m1 - s1);
                l1 *= corr;
                #pragma unroll
                for (int d = 0; d < 32; d++) o1[d] *= corr;
                m1 = s1;
            }
            const float p0 = __expf(s0 - m0);
            const float p1 = __expf(s1 - m1);
            l0 += p0; l1 += p1;

            const float4* Vr = (const float4*)sV[kk];
            #pragma unroll
            for (int f = 0; f < 8; f++) {
                const float4 vv = Vr[f];
                o0[f*4+0] += p0*vv.x; o0[f*4+1] += p0*vv.y; o0[f*4+2] += p0*vv.z; o0[f*4+3] += p0*vv.w;
                o1[f*4+0] += p1*vv.x; o1[f*4+1] += p1*vv.y; o1[f*4+2] += p1*vv.z; o1[f*4+3] += p1*vv.w;
            }
        }
    }

    const float inv0 = 1.0f / l0;
    const float inv1 = 1.0f / l1;
    #pragma unroll
    for (int f = 0; f < 8; f++) {
        float4 t0 = {o0[f*4]*inv0, o0[f*4+1]*inv0, o0[f*4+2]*inv0, o0[f*4+3]*inv0};
        float4 t1 = {o1[f*4]*inv1, o1[f*4+1]*inv1, o1[f*4+2]*inv1, o1[f*4+3]*inv1};
        *(float4*)(g_o + q0off + f*4) = t0;
        *(float4*)(g_o + q1off + f*4) = t1;
    }
}

// ---------------------------------------------------------------------------
// Kernel C: out = (g * o) @ Wo^T. Same register-tiled GEMM as proj.
// ---------------------------------------------------------------------------
__global__ __launch_bounds__(256) void out_kernel(float* __restrict__ out)
{
    __shared__ float sZ[C][68];
    __shared__ float sW[16][C];

    const int tid = threadIdx.x;
    const int r0  = blockIdx.x * 64;

    for (int idx = tid; idx < 64*128; idx += 256) {
        const int k = idx & 127, row = idx >> 7;
        const size_t off = (size_t)(r0 + row) * C + k;
        sZ[k][row] = g_g[off] * g_o[off];
    }
    __syncthreads();

    const int tr = tid >> 4;
    const int tc = tid & 15;

    float acc[32];
    #pragma unroll
    for (int i = 0; i < 32; i++) acc[i] = 0.0f;

    for (int kb = 0; kb < 8; kb++) {
        __syncthreads();
        #pragma unroll
        for (int l = 0; l < 8; l++) {
            const int idx = tid + l * 256;
            const int c = idx & 127, k = idx >> 7;
            sW[k][c] = g_Wt[4][kb*16 + k][c];
        }
        __syncthreads();

        #pragma unroll
        for (int k = 0; k < 16; k++) {
            const float4 a  = *(const float4*)&sZ[kb*16 + k][tr*4];
            const float4 b0 = *(const float4*)&sW[k][tc*8];
            const float4 b1 = *(const float4*)&sW[k][tc*8 + 4];
            const float av[4] = {a.x, a.y, a.z, a.w};
            const float bv[8] = {b0.x,b0.y,b0.z,b0.w,b1.x,b1.y,b1.z,b1.w};
            #pragma unroll
            for (int r = 0; r < 4; r++)
                #pragma unroll
                for (int cc = 0; cc < 8; cc++)
                    acc[r*8+cc] += av[r] * bv[cc];
        }
    }

    #pragma unroll
    for (int r = 0; r < 4; r++) {
        const size_t row = (size_t)(r0 + tr*4 + r);
        float4 o0 = {acc[r*8+0], acc[r*8+1], acc[r*8+2], acc[r*8+3]};
        float4 o1 = {acc[r*8+4], acc[r*8+5], acc[r*8+6], acc[r*8+7]};
        *(float4*)&out[row*C + tc*8    ] = o0;
        *(float4*)&out[row*C + tc*8 + 4] = o1;
    }
}

// ---------------------------------------------------------------------------
extern "C" void kernel_launch(void* const* d_in, const int* in_sizes, int n_in,
                              void* d_out, int out_size)
{
    const float* z   = (const float*)d_in[0];
    const float* lnw = (const float*)d_in[1];
    const float* lnb = (const float*)d_in[2];
    const float* Wq  = (const float*)d_in[3];
    const float* Wk  = (const float*)d_in[4];
    const float* Wv  = (const float*)d_in[5];
    // d_in[6] = Wb: constant over softmax axis -> exact no-op, skipped.
    const float* Wg  = (const float*)d_in[7];
    const float* Wo  = (const float*)d_in[8];
    float* out = (float*)d_out;

    transpose_w<<<dim3(4,4,5), dim3(32,8)>>>(Wq, Wk, Wv, Wg, Wo);
    proj_kernel<<<NROW/64, 256>>>(z, lnw, lnb);
    attn_kernel<<<dim3(S, H), 128>>>();
    out_kernel<<<NROW/64, 256>>>(out);
}

// round 3
// speedup vs baseline: 1.7481x; 1.3247x over previous
#include <cuda_runtime.h>

typedef unsigned long long ull;

#define S 256
#define C 128
#define NROW (S*S)
#define ATTN_SCALE 0.1767766952966369f   // 1/sqrt(32)
#define LN_EPS 1e-5f

// Scratch (device globals: allocation-free per harness rules)
__device__ float g_q[NROW*C];
__device__ float g_k[NROW*C];
__device__ float g_v[NROW*C];
__device__ float g_g[NROW*C];            // sigmoid(z @ Wg^T)
__device__ float g_o[NROW*C];            // attention output
__device__ float g_Wt[5][C][C];          // k-major weights: g_Wt[m][k][c] = W_m[c][k]

// ---- packed f32x2 helpers (sm_100a FFMA2 path) ----
__device__ __forceinline__ ull ffma2(ull a, ull b, ull c) {
    ull d; asm("fma.rn.f32x2 %0, %1, %2, %3;" : "=l"(d) : "l"(a), "l"(b), "l"(c)); return d;
}
__device__ __forceinline__ ull fmul2(ull a, ull b) {
    ull d; asm("mul.rn.f32x2 %0, %1, %2;" : "=l"(d) : "l"(a), "l"(b)); return d;
}
__device__ __forceinline__ ull fpack(float lo, float hi) {
    ull d; asm("mov.b64 %0, {%1, %2};" : "=l"(d) : "f"(lo), "f"(hi)); return d;
}
__device__ __forceinline__ void funpack(ull p, float& lo, float& hi) {
    asm("mov.b64 {%0, %1}, %2;" : "=f"(lo), "=f"(hi) : "l"(p));
}

extern __shared__ float dynsmem[];

// ---------------------------------------------------------------------------
// Kernel T: transpose the 5 weight matrices into k-major layout (tiny).
// ---------------------------------------------------------------------------
__global__ void transpose_w(const float* __restrict__ Wq, const float* __restrict__ Wk,
                            const float* __restrict__ Wv, const float* __restrict__ Wg,
                            const float* __restrict__ Wo)
{
    __shared__ float t[32][33];
    const float* Ws[5] = {Wq, Wk, Wv, Wg, Wo};
    const float* W = Ws[blockIdx.z];
    const int cb = blockIdx.x * 32;
    const int kb = blockIdx.y * 32;
    const int tx = threadIdx.x, ty = threadIdx.y;

    #pragma unroll
    for (int i = ty; i < 32; i += 8)
        t[i][tx] = W[(cb + i) * C + kb + tx];
    __syncthreads();
    #pragma unroll
    for (int i = ty; i < 32; i += 8)
        g_Wt[blockIdx.z][kb + i][cb + tx] = t[tx][i];
}

// ---------------------------------------------------------------------------
// Kernel A: fused LayerNorm + 4 projections. 128 rows/block, 256 threads.
// Per thread: 8 rows (4 row-pairs, packed f32x2) x 8 cols.
// smem: sZ[128][132] (k-major LN output) + sW[32][128] k-chunk of weights.
// ---------------------------------------------------------------------------
__global__ __launch_bounds__(256) void proj_kernel(
    const float* __restrict__ z,
    const float* __restrict__ lnw, const float* __restrict__ lnb)
{
    float* sZ = dynsmem;             // [128][132]  (k, row)
    float* sW = dynsmem + 128*132;   // [32][128]   (k, col)

    const int tid  = threadIdx.x;
    const int warp = tid >> 5;
    const int lane = tid & 31;
    const int r0   = blockIdx.x * 128;

    // ---- LayerNorm: 8 warps x 16 rows each ----
    for (int rr = 0; rr < 16; rr++) {
        const int rl = warp * 16 + rr;
        const float* zr = z + (size_t)(r0 + rl) * C;
        float v0 = zr[lane], v1 = zr[lane+32], v2 = zr[lane+64], v3 = zr[lane+96];
        float s  = v0+v1+v2+v3;
        float sq = v0*v0+v1*v1+v2*v2+v3*v3;
        #pragma unroll
        for (int off = 16; off; off >>= 1) {
            s  += __shfl_xor_sync(0xffffffffu, s,  off);
            sq += __shfl_xor_sync(0xffffffffu, sq, off);
        }
        const float mu  = s * (1.0f/128.0f);
        const float var = sq * (1.0f/128.0f) - mu*mu;
        const float rs  = rsqrtf(var + LN_EPS);
        sZ[(lane     )*132 + rl] = (v0-mu)*rs*lnw[lane     ] + lnb[lane     ];
        sZ[(lane + 32)*132 + rl] = (v1-mu)*rs*lnw[lane + 32] + lnb[lane + 32];
        sZ[(lane + 64)*132 + rl] = (v2-mu)*rs*lnw[lane + 64] + lnb[lane + 64];
        sZ[(lane + 96)*132 + rl] = (v3-mu)*rs*lnw[lane + 96] + lnb[lane + 96];
    }
    __syncthreads();

    const int tr = tid >> 4;   // 0..15 -> rows tr*8 .. tr*8+7 (4 packed pairs)
    const int tc = tid & 15;   // 0..15 -> cols tc*8 .. tc*8+7

    for (int grp = 0; grp < 4; grp++) {
        ull acc[32];
        #pragma unroll
        for (int i = 0; i < 32; i++) acc[i] = 0ull;

        for (int kb = 0; kb < 4; kb++) {
            __syncthreads();
            {   // stage 32x128 weight chunk: 16 consecutive floats per thread
                const float* src = &g_Wt[grp][kb*32 + (tid>>3)][(tid&7)*16];
                float* dst = &sW[(tid>>3)*128 + (tid&7)*16];
                #pragma unroll
                for (int q4 = 0; q4 < 4; q4++)
                    *(float4*)(dst + q4*4) = *(const float4*)(src + q4*4);
            }
            __syncthreads();

            #pragma unroll
            for (int k = 0; k < 32; k++) {
                const ull* zp = (const ull*)&sZ[(kb*32 + k)*132 + tr*8];
                const ull ap0 = zp[0], ap1 = zp[1], ap2 = zp[2], ap3 = zp[3];
                const float* wr = &sW[k*128 + tc*8];
                const float4 B0 = *(const float4*)wr;
                const float4 B1 = *(const float4*)(wr + 4);
                ull bd[8];
                bd[0]=fpack(B0.x,B0.x); bd[1]=fpack(B0.y,B0.y);
                bd[2]=fpack(B0.z,B0.z); bd[3]=fpack(B0.w,B0.w);
                bd[4]=fpack(B1.x,B1.x); bd[5]=fpack(B1.y,B1.y);
                bd[6]=fpack(B1.z,B1.z); bd[7]=fpack(B1.w,B1.w);
                #pragma unroll
                for (int c = 0; c < 8; c++) {
                    acc[0*8+c] = ffma2(ap0, bd[c], acc[0*8+c]);
                    acc[1*8+c] = ffma2(ap1, bd[c], acc[1*8+c]);
                    acc[2*8+c] = ffma2(ap2, bd[c], acc[2*8+c]);
                    acc[3*8+c] = ffma2(ap3, bd[c], acc[3*8+c]);
                }
            }
        }

        float* O = (grp == 0) ? g_q : (grp == 1) ? g_k : (grp == 2) ? g_v : g_g;
        #pragma unroll
        for (int rp = 0; rp < 4; rp++) {
            float lo[8], hi[8];
            #pragma unroll
            for (int c = 0; c < 8; c++) funpack(acc[rp*8+c], lo[c], hi[c]);
            if (grp == 3) {
                #pragma unroll
                for (int c = 0; c < 8; c++) {
                    lo[c] = 1.0f/(1.0f + __expf(-lo[c]));
                    hi[c] = 1.0f/(1.0f + __expf(-hi[c]));
                }
            }
            const size_t row0 = (size_t)(r0 + tr*8 + rp*2);
            float4 l0v = {lo[0],lo[1],lo[2],lo[3]}, l1v = {lo[4],lo[5],lo[6],lo[7]};
            float4 h0v = {hi[0],hi[1],hi[2],hi[3]}, h1v = {hi[4],hi[5],hi[6],hi[7]};
            *(float4*)&O[ row0   *C + tc*8    ] = l0v;
            *(float4*)&O[ row0   *C + tc*8 + 4] = l1v;
            *(float4*)&O[(row0+1)*C + tc*8    ] = h0v;
            *(float4*)&O[(row0+1)*C + tc*8 + 4] = h1v;
        }
    }
}

// ---------------------------------------------------------------------------
// Kernel B: attention. Block = (j,h); 128 threads, 2 queries per thread.
// K stored TRANSPOSED in smem (sKt[d][kk]) so kk-pairs are contiguous ->
// packed score accumulation with no horizontal reduction. V natural layout ->
// packed-over-d PV accumulation. 4 keys per iteration.
// Bias term dropped: constant over softmax axis -> exact no-op.
// ---------------------------------------------------------------------------
__global__ __launch_bounds__(128) void attn_kernel()
{
    float* sKt = dynsmem;              // [32][260]  (d, kk)
    float* sV  = dynsmem + 32*260;     // [256][32]  (kk, d)

    const int j   = blockIdx.x;
    const int h   = blockIdx.y;
    const int tid = threadIdx.x;

    const size_t kvbase = (size_t)j * S * C + h * 32;   // row (j*S + kk)

    // K transposed into smem
    for (int idx = tid; idx < 256*8; idx += 128) {
        const int row = idx >> 3, f = idx & 7;
        const float4 t = *(const float4*)(g_k + kvbase + (size_t)row * C + f*4);
        sKt[(4*f+0)*260 + row] = t.x;
        sKt[(4*f+1)*260 + row] = t.y;
        sKt[(4*f+2)*260 + row] = t.z;
        sKt[(4*f+3)*260 + row] = t.w;
    }
    // V natural
    for (int idx = tid; idx < 256*8; idx += 128) {
        const int row = idx >> 3, f = idx & 7;
        *(float4*)&sV[row*32 + f*4] =
            *(const float4*)(g_v + kvbase + (size_t)row * C + f*4);
    }

    // Two queries per thread: i0 = tid, i1 = tid + 128
    float q0[32], q1[32];
    const size_t q0off = ((size_t)tid * S + j) * C + h * 32;
    const size_t q1off = q0off + (size_t)128 * S * C;
    #pragma unroll
    for (int f = 0; f < 8; f++) {
        const float4 t0 = *(const float4*)(g_q + q0off + f*4);
        const float4 t1 = *(const float4*)(g_q + q1off + f*4);
        q0[f*4+0]=t0.x; q0[f*4+1]=t0.y; q0[f*4+2]=t0.z; q0[f*4+3]=t0.w;
        q1[f*4+0]=t1.x; q1[f*4+1]=t1.y; q1[f*4+2]=t1.z; q1[f*4+3]=t1.w;
    }

    ull o0[16], o1[16];
    #pragma unroll
    for (int i = 0; i < 16; i++) { o0[i] = 0ull; o1[i] = 0ull; }
    float m0 = -1e30f, l0 = 0.0f, m1 = -1e30f, l1 = 0.0f;

    __syncthreads();

    for (int it = 0; it < 64; it++) {
        const int kk0 = it * 4;

        // ---- scores for 4 keys x 2 queries, packed over kk-pairs ----
        ull s00 = 0ull, s01 = 0ull, s10 = 0ull, s11 = 0ull;
        #pragma unroll
        for (int d = 0; d < 32; d++) {
            const float* kr = &sKt[d*260 + kk0];
            const ull k01 = *(const ull*)kr;
            const ull k23 = *(const ull*)(kr + 2);
            const ull qa = fpack(q0[d], q0[d]);
            const ull qb = fpack(q1[d], q1[d]);
            s00 = ffma2(qa, k01, s00);
            s01 = ffma2(qa, k23, s01);
            s10 = ffma2(qb, k01, s10);
            s11 = ffma2(qb, k23, s11);
        }
        float a0,a1,a2,a3, b0,b1,b2,b3;
        funpack(s00, a0, a1); funpack(s01, a2, a3);
        funpack(s10, b0, b1); funpack(s11, b2, b3);
        a0 *= ATTN_SCALE; a1 *= ATTN_SCALE; a2 *= ATTN_SCALE; a3 *= ATTN_SCALE;
        b0 *= ATTN_SCALE; b1 *= ATTN_SCALE; b2 *= ATTN_SCALE; b3 *= ATTN_SCALE;

        // ---- online softmax, query 0 ----
        {
            const float nm = fmaxf(fmaxf(a0,a1), fmaxf(a2,a3));
            if (nm > m0) {
                const float corr = __expf(m0 - nm);
                m0 = nm; l0 *= corr;
                const ull cp = fpack(corr, corr);
                #pragma unroll
                for (int i = 0; i < 16; i++) o0[i] = fmul2(o0[i], cp);
            }
        }
        const float p00 = __expf(a0 - m0), p01 = __expf(a1 - m0);
        const float p02 = __expf(a2 - m0), p03 = __expf(a3 - m0);
        l0 += (p00 + p01) + (p02 + p03);

        // ---- online softmax, query 1 ----
        {
            const float nm = fmaxf(fmaxf(b0,b1), fmaxf(b2,b3));
            if (nm > m1) {
                const float corr = __expf(m1 - nm);
                m1 = nm; l1 *= corr;
                const ull cp = fpack(corr, corr);
                #pragma unroll
                for (int i = 0; i < 16; i++) o1[i] = fmul2(o1[i], cp);
            }
        }
        const float p10 = __expf(b0 - m1), p11 = __expf(b1 - m1);
        const float p12 = __expf(b2 - m1), p13 = __expf(b3 - m1);
        l1 += (p10 + p11) + (p12 + p13);

        // ---- PV: packed over d ----
        const float pq0[4] = {p00, p01, p02, p03};
        const float pq1[4] = {p10, p11, p12, p13};
        #pragma unroll
        for (int kki = 0; kki < 4; kki++) {
            const ull* vr = (const ull*)&sV[(kk0 + kki)*32];
            const ull pp0 = fpack(pq0[kki], pq0[kki]);
            const ull pp1 = fpack(pq1[kki], pq1[kki]);
            #pragma unroll
            for (int i = 0; i < 16; i++) {
                o0[i] = ffma2(pp0, vr[i], o0[i]);
                o1[i] = ffma2(pp1, vr[i], o1[i]);
            }
        }
    }

    const float inv0 = 1.0f / l0;
    const float inv1 = 1.0f / l1;
    float r0v[32], r1v[32];
    #pragma unroll
    for (int i = 0; i < 16; i++) {
        funpack(o0[i], r0v[2*i], r0v[2*i+1]);
        funpack(o1[i], r1v[2*i], r1v[2*i+1]);
    }
    #pragma unroll
    for (int f = 0; f < 8; f++) {
        float4 t0 = {r0v[f*4]*inv0, r0v[f*4+1]*inv0, r0v[f*4+2]*inv0, r0v[f*4+3]*inv0};
        float4 t1 = {r1v[f*4]*inv1, r1v[f*4+1]*inv1, r1v[f*4+2]*inv1, r1v[f*4+3]*inv1};
        *(float4*)(g_o + q0off + f*4) = t0;
        *(float4*)(g_o + q1off + f*4) = t1;
    }
}

// ---------------------------------------------------------------------------
// Kernel C: out = (g * o) @ Wo^T. Same packed GEMM as proj (single weight).
// ---------------------------------------------------------------------------
__global__ __launch_bounds__(256) void out_kernel(float* __restrict__ out)
{
    float* sZ = dynsmem;
    float* sW = dynsmem + 128*132;

    const int tid = threadIdx.x;
    const int r0  = blockIdx.x * 128;

    for (int idx = tid; idx < 128*128; idx += 256) {
        const int row = idx >> 7, k = idx & 127;
        const size_t off = (size_t)(r0 + row) * C + k;
        sZ[k*132 + row] = g_g[off] * g_o[off];
    }
    __syncthreads();

    const int tr = tid >> 4;
    const int tc = tid & 15;

    ull acc[32];
    #pragma unroll
    for (int i = 0; i < 32; i++) acc[i] = 0ull;

    for (int kb = 0; kb < 4; kb++) {
        __syncthreads();
        {
            const float* src = &g_Wt[4][kb*32 + (tid>>3)][(tid&7)*16];
            float* dst = &sW[(tid>>3)*128 + (tid&7)*16];
            #pragma unroll
            for (int q4 = 0; q4 < 4; q4++)
                *(float4*)(dst + q4*4) = *(const float4*)(src + q4*4);
        }
        __syncthreads();

        #pragma unroll
        for (int k = 0; k < 32; k++) {
            const ull* zp = (const ull*)&sZ[(kb*32 + k)*132 + tr*8];
            const ull ap0 = zp[0], ap1 = zp[1], ap2 = zp[2], ap3 = zp[3];
            const float* wr = &sW[k*128 + tc*8];
            const float4 B0 = *(const float4*)wr;
            const float4 B1 = *(const float4*)(wr + 4);
            ull bd[8];
            bd[0]=fpack(B0.x,B0.x); bd[1]=fpack(B0.y,B0.y);
            bd[2]=fpack(B0.z,B0.z); bd[3]=fpack(B0.w,B0.w);
            bd[4]=fpack(B1.x,B1.x); bd[5]=fpack(B1.y,B1.y);
            bd[6]=fpack(B1.z,B1.z); bd[7]=fpack(B1.w,B1.w);
            #pragma unroll
            for (int c = 0; c < 8; c++) {
                acc[0*8+c] = ffma2(ap0, bd[c], acc[0*8+c]);
                acc[1*8+c] = ffma2(ap1, bd[c], acc[1*8+c]);
                acc[2*8+c] = ffma2(ap2, bd[c], acc[2*8+c]);
                acc[3*8+c] = ffma2(ap3, bd[c], acc[3*8+c]);
            }
        }
    }

    #pragma unroll
    for (int rp = 0; rp < 4; rp++) {
        float lo[8], hi[8];
        #pragma unroll
        for (int c = 0; c < 8; c++) funpack(acc[rp*8+c], lo[c], hi[c]);
        const size_t row0 = (size_t)(r0 + tr*8 + rp*2);
        float4 l0v = {lo[0],lo[1],lo[2],lo[3]}, l1v = {lo[4],lo[5],lo[6],lo[7]};
        float4 h0v = {hi[0],hi[1],hi[2],hi[3]}, h1v = {hi[4],hi[5],hi[6],hi[7]};
        *(float4*)&out[ row0   *C + tc*8    ] = l0v;
        *(float4*)&out[ row0   *C + tc*8 + 4] = l1v;
        *(float4*)&out[(row0+1)*C + tc*8    ] = h0v;
        *(float4*)&out[(row0+1)*C + tc*8 + 4] = h1v;
    }
}

// ---------------------------------------------------------------------------
extern "C" void kernel_launch(void* const* d_in, const int* in_sizes, int n_in,
                              void* d_out, int out_size)
{
    const float* z   = (const float*)d_in[0];
    const float* lnw = (const float*)d_in[1];
    const float* lnb = (const float*)d_in[2];
    const float* Wq  = (const float*)d_in[3];
    const float* Wk  = (const float*)d_in[4];
    const float* Wv  = (const float*)d_in[5];
    // d_in[6] = Wb: constant over softmax axis -> exact no-op, skipped.
    const float* Wg  = (const float*)d_in[7];
    const float* Wo  = (const float*)d_in[8];
    float* out = (float*)d_out;

    const int smemGemm = (128*132 + 32*128) * sizeof(float);   // 83968 B
    const int smemAttn = (32*260 + 256*32) * sizeof(float);    // 66048 B
    static bool attr_done = false;
    if (!attr_done) {
        cudaFuncSetAttribute(proj_kernel, cudaFuncAttributeMaxDynamicSharedMemorySize, smemGemm);
        cudaFuncSetAttribute(out_kernel,  cudaFuncAttributeMaxDynamicSharedMemorySize, smemGemm);
        cudaFuncSetAttribute(attn_kernel, cudaFuncAttributeMaxDynamicSharedMemorySize, smemAttn);
        attr_done = true;
    }

    transpose_w<<<dim3(4,4,5), dim3(32,8)>>>(Wq, Wk, Wv, Wg, Wo);
    proj_kernel<<<NROW/128, 256, smemGemm>>>(z, lnw, lnb);
    attn_kernel<<<dim3(S, 4), 128, smemAttn>>>();
    out_kernel<<<NROW/128, 256, smemGemm>>>(out);
}

// round 4
// speedup vs baseline: 3.0020x; 1.7173x over previous
#include <cuda_runtime.h>
#include <cuda_bf16.h>
#include <cstdint>

#define S 256
#define C 128
#define NROW (S*S)
#define ATTN_SCALE 0.1767766952966369f   // 1/sqrt(32)
#define LN_EPS 1e-5f

// ---------------- scratch (device globals; allocation-free) ----------------
__device__ uint32_t g_W1[5][C*C/2], g_W2[5][C*C/2];   // bf16 pairs, [c][k/2]
__device__ uint32_t g_q1[NROW*C/2], g_q2[NROW*C/2];
__device__ uint32_t g_k1[NROW*C/2], g_k2[NROW*C/2];
__device__ uint32_t g_v1[NROW*C/2], g_v2[NROW*C/2];
__device__ float    g_g [NROW*C];
__device__ uint32_t g_go1[NROW*C/2], g_go2[NROW*C/2];

// ---------------- helpers ----------------
__device__ __forceinline__ uint32_t smem_u32(const void* p) {
    return (uint32_t)__cvta_generic_to_shared(p);
}
__device__ __forceinline__ void ldsm4(uint32_t* r, uint32_t addr) {
    asm volatile("ldmatrix.sync.aligned.m8n8.x4.shared.b16 {%0,%1,%2,%3},[%4];"
        : "=r"(r[0]), "=r"(r[1]), "=r"(r[2]), "=r"(r[3]) : "r"(addr));
}
__device__ __forceinline__ void ldsm4t(uint32_t* r, uint32_t addr) {
    asm volatile("ldmatrix.sync.aligned.m8n8.x4.trans.shared.b16 {%0,%1,%2,%3},[%4];"
        : "=r"(r[0]), "=r"(r[1]), "=r"(r[2]), "=r"(r[3]) : "r"(addr));
}
__device__ __forceinline__ void mma16816(float* d, const uint32_t* a, const uint32_t* b) {
    asm volatile("mma.sync.aligned.m16n8k16.row.col.f32.bf16.bf16.f32 "
        "{%0,%1,%2,%3},{%4,%5,%6,%7},{%8,%9},{%0,%1,%2,%3};"
        : "+f"(d[0]), "+f"(d[1]), "+f"(d[2]), "+f"(d[3])
        : "r"(a[0]), "r"(a[1]), "r"(a[2]), "r"(a[3]), "r"(b[0]), "r"(b[1]));
}
// pack (lo=x0, hi=x1) into bf16x2
__device__ __forceinline__ uint32_t cvt2(float x0, float x1) {
    uint32_t r; asm("cvt.rn.bf16x2.f32 %0, %1, %2;" : "=r"(r) : "f"(x1), "f"(x0)); return r;
}
// split pair into leading bf16x2 + residual bf16x2
__device__ __forceinline__ void split_pair(float x0, float x1, uint32_t& hi, uint32_t& lo) {
    hi = cvt2(x0, x1);
    const float f0 = __uint_as_float(hi << 16);
    const float f1 = __uint_as_float(hi & 0xffff0000u);
    lo = cvt2(x0 - f0, x1 - f1);
}

extern __shared__ char dynsmem[];

// GEMM smem layout constants: rows padded to 272B (136 bf16), 16B aligned, conflict-free LDSM
#define GPAD 272
#define APAD 80      // attn tiles: 32 bf16 rows padded to 80B

// ---------------------------------------------------------------------------
// split_w: split 5 weight matrices into leading/residual bf16 (no transpose:
// W[c][k] row-major is exactly the col-major B operand of mma row.col).
// ---------------------------------------------------------------------------
__global__ void split_w(const float* __restrict__ Wq, const float* __restrict__ Wk,
                        const float* __restrict__ Wv, const float* __restrict__ Wg,
                        const float* __restrict__ Wo)
{
    const float* Ws[5] = {Wq, Wk, Wv, Wg, Wo};
    const int m = blockIdx.y;
    const int p = blockIdx.x * 256 + threadIdx.x;   // pair index, 8192 per matrix
    const float x0 = Ws[m][2*p], x1 = Ws[m][2*p+1];
    uint32_t hi, lo; split_pair(x0, x1, hi, lo);
    g_W1[m][p] = hi; g_W2[m][p] = lo;
}

// ---------------------------------------------------------------------------
// proj_kernel: LN + 4 projections via bf16x3 mma. 128 rows x 128 cols / block.
// 8 warps as 4(m) x 2(n): warp tile 32 x 64.
// ---------------------------------------------------------------------------
__global__ __launch_bounds__(256) void proj_kernel(
    const float* __restrict__ z,
    const float* __restrict__ lnw, const float* __restrict__ lnb)
{
    char* sA1 = dynsmem;
    char* sA2 = dynsmem + 128*GPAD;
    char* sB1 = dynsmem + 2*128*GPAD;
    char* sB2 = dynsmem + 3*128*GPAD;

    const int tid = threadIdx.x, warp = tid >> 5, lane = tid & 31;
    const int r0 = blockIdx.x * 128;

    // ---- LayerNorm -> split bf16 into sA1/sA2. lane owns c = 4*lane..+3 ----
    const float4 w4 = *(const float4*)(lnw + lane*4);
    const float4 b4 = *(const float4*)(lnb + lane*4);
    for (int rr = 0; rr < 16; rr++) {
        const int rl = warp*16 + rr;
        const float4 v = *(const float4*)(z + (size_t)(r0 + rl)*C + lane*4);
        float s  = v.x+v.y+v.z+v.w;
        float sq = v.x*v.x+v.y*v.y+v.z*v.z+v.w*v.w;
        #pragma unroll
        for (int off = 16; off; off >>= 1) {
            s  += __shfl_xor_sync(0xffffffffu, s,  off);
            sq += __shfl_xor_sync(0xffffffffu, sq, off);
        }
        const float mu  = s * (1.0f/128.0f);
        const float var = sq * (1.0f/128.0f) - mu*mu;
        const float rs  = rsqrtf(var + LN_EPS);
        const float y0 = (v.x-mu)*rs*w4.x + b4.x;
        const float y1 = (v.y-mu)*rs*w4.y + b4.y;
        const float y2 = (v.z-mu)*rs*w4.z + b4.z;
        const float y3 = (v.w-mu)*rs*w4.w + b4.w;
        uint32_t h0,l0,h1,l1;
        split_pair(y0,y1,h0,l0); split_pair(y2,y3,h1,l1);
        uint2 hv = {h0,h1}, lv = {l0,l1};
        *(uint2*)(sA1 + rl*GPAD + lane*8) = hv;
        *(uint2*)(sA2 + rl*GPAD + lane*8) = lv;
    }

    const int wm = warp >> 1, wn = warp & 1;
    const uint32_t a1b = smem_u32(sA1), a2b = smem_u32(sA2);
    const uint32_t b1b = smem_u32(sB1), b2b = smem_u32(sB2);
    const int g = lane >> 3, r = lane & 7;

    for (int grp = 0; grp < 4; grp++) {
        __syncthreads();
        #pragma unroll
        for (int i = 0; i < 8; i++) {           // stage W split (128 rows x 16 16B-chunks)
            const int ch = tid + i*256;
            const int row = ch >> 4, q = ch & 15;
            *(uint4*)(sB1 + row*GPAD + q*16) = *(const uint4*)(&g_W1[grp][row*64 + q*4]);
            *(uint4*)(sB2 + row*GPAD + q*16) = *(const uint4*)(&g_W2[grp][row*64 + q*4]);
        }
        __syncthreads();

        float acc[2][8][4];
        #pragma unroll
        for (int a = 0; a < 2; a++)
            #pragma unroll
            for (int b = 0; b < 8; b++)
                #pragma unroll
                for (int c = 0; c < 4; c++) acc[a][b][c] = 0.0f;

        for (int k32 = 0; k32 < 4; k32++) {
            uint32_t A1[2][2][4], A2[2][2][4];
            #pragma unroll
            for (int mf = 0; mf < 2; mf++) {
                const int row0 = wm*32 + mf*16;
                #pragma unroll
                for (int kf = 0; kf < 2; kf++) {
                    const uint32_t off = (row0 + (g&1)*8 + r)*GPAD + (k32*32 + kf*16 + (g>>1)*8)*2;
                    ldsm4(A1[mf][kf], a1b + off);
                    ldsm4(A2[mf][kf], a2b + off);
                }
            }
            #pragma unroll
            for (int nf = 0; nf < 8; nf++) {
                const int col0 = wn*64 + nf*8;
                const uint32_t off = (col0 + r)*GPAD + (k32*32 + g*8)*2;
                uint32_t B1[4], B2[4];
                ldsm4(B1, b1b + off);
                ldsm4(B2, b2b + off);
                #pragma unroll
                for (int mf = 0; mf < 2; mf++)
                    #pragma unroll
                    for (int kf = 0; kf < 2; kf++) {
                        mma16816(acc[mf][nf], A1[mf][kf], &B1[kf*2]);
                        mma16816(acc[mf][nf], A1[mf][kf], &B2[kf*2]);
                        mma16816(acc[mf][nf], A2[mf][kf], &B1[kf*2]);
                    }
            }
        }

        // ---- epilogue ----
        uint32_t* O1 = (grp == 0) ? g_q1 : (grp == 1) ? g_k1 : g_v1;
        uint32_t* O2 = (grp == 0) ? g_q2 : (grp == 1) ? g_k2 : g_v2;
        #pragma unroll
        for (int mf = 0; mf < 2; mf++) {
            const int row = r0 + wm*32 + mf*16 + (lane>>2);
            #pragma unroll
            for (int nf = 0; nf < 8; nf++) {
                const int col = wn*64 + nf*8 + 2*(lane&3);
                float c0 = acc[mf][nf][0], c1 = acc[mf][nf][1];
                float c2 = acc[mf][nf][2], c3 = acc[mf][nf][3];
                if (grp == 0) { c0*=ATTN_SCALE; c1*=ATTN_SCALE; c2*=ATTN_SCALE; c3*=ATTN_SCALE; }
                if (grp == 3) {
                    float2 s0 = {1.0f/(1.0f+__expf(-c0)), 1.0f/(1.0f+__expf(-c1))};
                    float2 s1 = {1.0f/(1.0f+__expf(-c2)), 1.0f/(1.0f+__expf(-c3))};
                    *(float2*)(g_g + (size_t)row*C + col)     = s0;
                    *(float2*)(g_g + (size_t)(row+8)*C + col) = s1;
                } else {
                    uint32_t hi, lo;
                    split_pair(c0, c1, hi, lo);
                    O1[(size_t)row*64 + (col>>1)] = hi;
                    O2[(size_t)row*64 + (col>>1)] = lo;
                    split_pair(c2, c3, hi, lo);
                    O1[(size_t)(row+8)*64 + (col>>1)] = hi;
                    O2[(size_t)(row+8)*64 + (col>>1)] = lo;
                }
            }
        }
    }
}

// ---------------------------------------------------------------------------
// attn_kernel: block = (j,h); 8 warps x 32 queries. bf16x3 mma flash attention.
// Q pre-scaled. Bias dropped (softmax no-op). Epilogue fuses g*o + bf16 split.
// ---------------------------------------------------------------------------
__global__ __launch_bounds__(256) void attn_kernel()
{
    char* sQ1 = dynsmem;
    char* sQ2 = dynsmem + 1*256*APAD;
    char* sK1 = dynsmem + 2*256*APAD;
    char* sK2 = dynsmem + 3*256*APAD;
    char* sV1 = dynsmem + 4*256*APAD;
    char* sV2 = dynsmem + 5*256*APAD;

    const int tid = threadIdx.x, warp = tid >> 5, lane = tid & 31;
    const int j = blockIdx.x, h = blockIdx.y;

    // ---- staging: thread t owns row t of each tile ----
    {
        const size_t qoff = (((size_t)tid*S + j)*C + h*32) * 2;   // bytes
        const size_t koff = (((size_t)j*S + tid)*C + h*32) * 2;
        #pragma unroll
        for (int q = 0; q < 4; q++) {
            *(uint4*)(sQ1 + tid*APAD + q*16) = *(const uint4*)((const char*)g_q1 + qoff + q*16);
            *(uint4*)(sQ2 + tid*APAD + q*16) = *(const uint4*)((const char*)g_q2 + qoff + q*16);
            *(uint4*)(sK1 + tid*APAD + q*16) = *(const uint4*)((const char*)g_k1 + koff + q*16);
            *(uint4*)(sK2 + tid*APAD + q*16) = *(const uint4*)((const char*)g_k2 + koff + q*16);
            *(uint4*)(sV1 + tid*APAD + q*16) = *(const uint4*)((const char*)g_v1 + koff + q*16);
            *(uint4*)(sV2 + tid*APAD + q*16) = *(const uint4*)((const char*)g_v2 + koff + q*16);
        }
    }
    __syncthreads();

    const int g = lane >> 3, r = lane & 7;

    // ---- Q fragments (resident) ----
    uint32_t Qa1[2][2][4], Qa2[2][2][4];
    #pragma unroll
    for (int mf = 0; mf < 2; mf++)
        #pragma unroll
        for (int kf = 0; kf < 2; kf++) {
            const uint32_t off = (warp*32 + mf*16 + (g&1)*8 + r)*APAD + (kf*16 + (g>>1)*8)*2;
            ldsm4(Qa1[mf][kf], smem_u32(sQ1) + off);
            ldsm4(Qa2[mf][kf], smem_u32(sQ2) + off);
        }

    float O[2][4][4];
    #pragma unroll
    for (int a = 0; a < 2; a++)
        #pragma unroll
        for (int b = 0; b < 4; b++)
            #pragma unroll
            for (int c = 0; c < 4; c++) O[a][b][c] = 0.0f;
    float mrow[2][2] = {{-1e30f,-1e30f},{-1e30f,-1e30f}};
    float lrow[2][2] = {{0.f,0.f},{0.f,0.f}};

    const uint32_t k1b = smem_u32(sK1), k2b = smem_u32(sK2);
    const uint32_t v1b = smem_u32(sV1), v2b = smem_u32(sV2);

    for (int ch = 0; ch < 4; ch++) {
        const int n00 = ch*64;
        float sc[2][8][4];
        #pragma unroll
        for (int a = 0; a < 2; a++)
            #pragma unroll
            for (int b = 0; b < 8; b++)
                #pragma unroll
                for (int c = 0; c < 4; c++) sc[a][b][c] = 0.0f;

        // ---- QK^T ----
        #pragma unroll
        for (int nf = 0; nf < 8; nf++) {
            const uint32_t off = (n00 + nf*8 + r)*APAD + (g*8)*2;  // 4 tiles span d=0..31
            uint32_t B1[4], B2[4];
            ldsm4(B1, k1b + off);
            ldsm4(B2, k2b + off);
            #pragma unroll
            for (int mf = 0; mf < 2; mf++)
                #pragma unroll
                for (int kf = 0; kf < 2; kf++) {
                    mma16816(sc[mf][nf], Qa1[mf][kf], &B1[kf*2]);
                    mma16816(sc[mf][nf], Qa1[mf][kf], &B2[kf*2]);
                    mma16816(sc[mf][nf], Qa2[mf][kf], &B1[kf*2]);
                }
        }

        // ---- online softmax (per row; rows r=lane/4 and +8 per m-frag) ----
        #pragma unroll
        for (int mf = 0; mf < 2; mf++)
            #pragma unroll
            for (int hh = 0; hh < 2; hh++) {
                float mx = -1e30f;
                #pragma unroll
                for (int nf = 0; nf < 8; nf++)
                    mx = fmaxf(mx, fmaxf(sc[mf][nf][2*hh], sc[mf][nf][2*hh+1]));
                mx = fmaxf(mx, __shfl_xor_sync(0xffffffffu, mx, 1));
                mx = fmaxf(mx, __shfl_xor_sync(0xffffffffu, mx, 2));
                const float mo = mrow[mf][hh];
                const float mn = fmaxf(mo, mx);
                const float corr = __expf(mo - mn);
                lrow[mf][hh] *= corr;
                #pragma unroll
                for (int nf = 0; nf < 4; nf++) {
                    O[mf][nf][2*hh]   *= corr;
                    O[mf][nf][2*hh+1] *= corr;
                }
                mrow[mf][hh] = mn;
                float ps = 0.0f;
                #pragma unroll
                for (int nf = 0; nf < 8; nf++) {
                    const float p0 = __expf(sc[mf][nf][2*hh]   - mn);
                    const float p1 = __expf(sc[mf][nf][2*hh+1] - mn);
                    sc[mf][nf][2*hh] = p0; sc[mf][nf][2*hh+1] = p1;
                    ps += p0 + p1;
                }
                ps += __shfl_xor_sync(0xffffffffu, ps, 1);
                ps += __shfl_xor_sync(0xffffffffu, ps, 2);
                lrow[mf][hh] += ps;
            }

        // ---- P @ V ----
        #pragma unroll
        for (int kb = 0; kb < 4; kb++) {
            uint32_t Vb1[8], Vb2[8];
            const uint32_t offv = (n00 + kb*16 + (g&1)*8 + r)*APAD + ((g>>1)*8)*2;
            ldsm4t(&Vb1[0], v1b + offv);
            ldsm4t(&Vb1[4], v1b + offv + 32);   // d += 16
            ldsm4t(&Vb2[0], v2b + offv);
            ldsm4t(&Vb2[4], v2b + offv + 32);
            #pragma unroll
            for (int mf = 0; mf < 2; mf++) {
                uint32_t Pa1[4], Pa2[4];
                split_pair(sc[mf][2*kb  ][0], sc[mf][2*kb  ][1], Pa1[0], Pa2[0]);
                split_pair(sc[mf][2*kb  ][2], sc[mf][2*kb  ][3], Pa1[1], Pa2[1]);
                split_pair(sc[mf][2*kb+1][0], sc[mf][2*kb+1][1], Pa1[2], Pa2[2]);
                split_pair(sc[mf][2*kb+1][2], sc[mf][2*kb+1][3], Pa1[3], Pa2[3]);
                #pragma unroll
                for (int nf = 0; nf < 4; nf++) {
                    mma16816(O[mf][nf], Pa1, &Vb1[nf*2]);
                    mma16816(O[mf][nf], Pa1, &Vb2[nf*2]);
                    mma16816(O[mf][nf], Pa2, &Vb1[nf*2]);
                }
            }
        }
    }

    // ---- epilogue: normalize, gate, split, store ----
    #pragma unroll
    for (int mf = 0; mf < 2; mf++)
        #pragma unroll
        for (int hh = 0; hh < 2; hh++) {
            const float inv = 1.0f / lrow[mf][hh];
            const int i = 32*warp + 16*mf + 8*hh + (lane>>2);
            #pragma unroll
            for (int nf = 0; nf < 4; nf++) {
                const int d = nf*8 + 2*(lane&3);
                const size_t ga = ((size_t)i*S + j)*C + h*32 + d;
                const float2 gv = *(const float2*)(g_g + ga);
                const float x0 = gv.x * O[mf][nf][2*hh]   * inv;
                const float x1 = gv.y * O[mf][nf][2*hh+1] * inv;
                uint32_t hi, lo; split_pair(x0, x1, hi, lo);
                g_go1[ga>>1] = hi; g_go2[ga>>1] = lo;
            }
        }
}

// ---------------------------------------------------------------------------
// out_kernel: out = (g*o) @ Wo^T, bf16x3 mma. Inputs g_go1/2, weight grp 4.
// ---------------------------------------------------------------------------
__global__ __launch_bounds__(256) void out_kernel(float* __restrict__ out)
{
    char* sA1 = dynsmem;
    char* sA2 = dynsmem + 128*GPAD;
    char* sB1 = dynsmem + 2*128*GPAD;
    char* sB2 = dynsmem + 3*128*GPAD;

    const int tid = threadIdx.x, warp = tid >> 5, lane = tid & 31;
    const int r0 = blockIdx.x * 128;

    #pragma unroll
    for (int i = 0; i < 8; i++) {
        const int ch = tid + i*256;
        const int row = ch >> 4, q = ch & 15;
        *(uint4*)(sA1 + row*GPAD + q*16) = *(const uint4*)(&g_go1[(size_t)(r0+row)*64 + q*4]);
        *(uint4*)(sA2 + row*GPAD + q*16) = *(const uint4*)(&g_go2[(size_t)(r0+row)*64 + q*4]);
        *(uint4*)(sB1 + row*GPAD + q*16) = *(const uint4*)(&g_W1[4][row*64 + q*4]);
        *(uint4*)(sB2 + row*GPAD + q*16) = *(const uint4*)(&g_W2[4][row*64 + q*4]);
    }
    __syncthreads();

    const int wm = warp >> 1, wn = warp & 1;
    const uint32_t a1b = smem_u32(sA1), a2b = smem_u32(sA2);
    const uint32_t b1b = smem_u32(sB1), b2b = smem_u32(sB2);
    const int g = lane >> 3, r = lane & 7;

    float acc[2][8][4];
    #pragma unroll
    for (int a = 0; a < 2; a++)
        #pragma unroll
        for (int b = 0; b < 8; b++)
            #pragma unroll
            for (int c = 0; c < 4; c++) acc[a][b][c] = 0.0f;

    for (int k32 = 0; k32 < 4; k32++) {
        uint32_t A1[2][2][4], A2[2][2][4];
        #pragma unroll
        for (int mf = 0; mf < 2; mf++) {
            const int row0 = wm*32 + mf*16;
            #pragma unroll
            for (int kf = 0; kf < 2; kf++) {
                const uint32_t off = (row0 + (g&1)*8 + r)*GPAD + (k32*32 + kf*16 + (g>>1)*8)*2;
                ldsm4(A1[mf][kf], a1b + off);
                ldsm4(A2[mf][kf], a2b + off);
            }
        }
        #pragma unroll
        for (int nf = 0; nf < 8; nf++) {
            const int col0 = wn*64 + nf*8;
            const uint32_t off = (col0 + r)*GPAD + (k32*32 + g*8)*2;
            uint32_t B1[4], B2[4];
            ldsm4(B1, b1b + off);
            ldsm4(B2, b2b + off);
            #pragma unroll
            for (int mf = 0; mf < 2; mf++)
                #pragma unroll
                for (int kf = 0; kf < 2; kf++) {
                    mma16816(acc[mf][nf], A1[mf][kf], &B1[kf*2]);
                    mma16816(acc[mf][nf], A1[mf][kf], &B2[kf*2]);
                    mma16816(acc[mf][nf], A2[mf][kf], &B1[kf*2]);
                }
        }
    }

    #pragma unroll
    for (int mf = 0; mf < 2; mf++) {
        const int row = r0 + wm*32 + mf*16 + (lane>>2);
        #pragma unroll
        for (int nf = 0; nf < 8; nf++) {
            const int col = wn*64 + nf*8 + 2*(lane&3);
            float2 v0 = {acc[mf][nf][0], acc[mf][nf][1]};
            float2 v1 = {acc[mf][nf][2], acc[mf][nf][3]};
            *(float2*)(out + (size_t)row*C + col)     = v0;
            *(float2*)(out + (size_t)(row+8)*C + col) = v1;
        }
    }
}

// ---------------------------------------------------------------------------
extern "C" void kernel_launch(void* const* d_in, const int* in_sizes, int n_in,
                              void* d_out, int out_size)
{
    const float* z   = (const float*)d_in[0];
    const float* lnw = (const float*)d_in[1];
    const float* lnb = (const float*)d_in[2];
    const float* Wq  = (const float*)d_in[3];
    const float* Wk  = (const float*)d_in[4];
    const float* Wv  = (const float*)d_in[5];
    // d_in[6] = Wb: constant over softmax axis -> exact no-op, skipped.
    const float* Wg  = (const float*)d_in[7];
    const float* Wo  = (const float*)d_in[8];
    float* out = (float*)d_out;

    const int smemG = 4 * 128 * GPAD;   // 139264 B
    const int smemA = 6 * 256 * APAD;   // 122880 B
    static bool attr_done = false;
    if (!attr_done) {
        cudaFuncSetAttribute(proj_kernel, cudaFuncAttributeMaxDynamicSharedMemorySize, smemG);
        cudaFuncSetAttribute(out_kernel,  cudaFuncAttributeMaxDynamicSharedMemorySize, smemG);
        cudaFuncSetAttribute(attn_kernel, cudaFuncAttributeMaxDynamicSharedMemorySize, smemA);
        attr_done = true;
    }

    split_w<<<dim3(32, 5), 256>>>(Wq, Wk, Wv, Wg, Wo);
    proj_kernel<<<NROW/128, 256, smemG>>>(z, lnw, lnb);
    attn_kernel<<<dim3(S, 4), 256, smemA>>>();
    out_kernel<<<NROW/128, 256, smemG>>>(out);
}